// round 10
// baseline (speedup 1.0000x reference)
#include <cuda_runtime.h>

#define KCL   64
#define PD    32
#define NBLK  296
#define TILE  256
#define DETC  1e-16f
#define NENT  2240

typedef unsigned long long ull;

// ---- shared memory layout (bytes) ----
#define OFF_MUK2 0          // ull[1024]  mu_k packed cluster-pairs [p][pair]  8192 B
#define OFF_ASM  8192       // 256 rows * 18 ull (mu_phi, pitch 36 floats)   36864 B
#define OFF_GR   45056      // float[256*64] gamma row-major, XOR-swizzled   65536 B
#define OFF_EC   110592     // float[256] exp(lcp)
#define OFF_NA   111616     // float[256] ||x||^2
#define OFF_AK   112640     // float[64]
#define OFF_ICOV 112896     // float[64]
#define OFF_NB   113152     // float[64]
#define SMEM_BYTES 113408

// per-block partials, layout [block][entry]:
// 0..2047 = M[k][p], 2048..2111 = N_k, 2112..2175 = E_k, 2176..2239 = S2_k
__device__ float g_scratch[NBLK * NENT];
__device__ float g_acc[NENT];

__device__ __forceinline__ ull pk2(float lo, float hi) {
    ull u; asm("mov.b64 %0, {%1,%2};" : "=l"(u) : "f"(lo), "f"(hi)); return u;
}
__device__ __forceinline__ void upk2(ull u, float& lo, float& hi) {
    asm("mov.b64 {%0,%1}, %2;" : "=f"(lo), "=f"(hi) : "l"(u));
}
__device__ __forceinline__ ull fma2(ull a, ull b, ull c) {
    ull d; asm("fma.rn.f32x2 %0, %1, %2, %3;" : "=l"(d) : "l"(a), "l"(b), "l"(c));
    return d;
}

__global__ __launch_bounds__(256, 1)
void deeplpm_main(const float* __restrict__ mu_phi,
                  const float* __restrict__ lcp_g,
                  const float* __restrict__ pi_k,
                  const float* __restrict__ mu_k,
                  const float* __restrict__ lck_g,
                  float* __restrict__ gamma_out,
                  int N) {
    extern __shared__ unsigned char sm[];
    ull*   MUK2 = (ull*)(sm + OFF_MUK2);
    float* ASMf = (float*)(sm + OFF_ASM);   // pitch 36 floats per point
    ull*   ASMu = (ull*)(sm + OFF_ASM);     // pitch 18 ull per point
    float* GRf  = (float*)(sm + OFF_GR);    // pitch 64 floats, swizzled quads
    float* ECs  = (float*)(sm + OFF_EC);
    float* NAs  = (float*)(sm + OFF_NA);
    float* AK   = (float*)(sm + OFF_AK);
    float* ICOV = (float*)(sm + OFF_ICOV);
    float* NB   = (float*)(sm + OFF_NB);

    const int tid = threadIdx.x;

    // ---- init tables ----
    for (int idx = tid; idx < 1024; idx += 256) {
        int pr = idx & 31, p = idx >> 5;
        MUK2[p * 32 + pr] = pk2(mu_k[(2 * pr) * PD + p], mu_k[(2 * pr + 1) * PD + p]);
    }
    if (tid < KCL) {
        float lck = lck_g[tid];
        ICOV[tid] = __expf(-lck);
        AK[tid]   = pi_k[tid] * __expf(-16.0f * lck);
        float nb = 0.0f;
        #pragma unroll
        for (int p = 0; p < PD; ++p) { float v = mu_k[tid * PD + p]; nb = fmaf(v, v, nb); }
        NB[tid] = nb;
    }

    // GEMM1 roles: s = cluster half (32 clusters), pidx = point (2 lanes/point)
    const int s    = tid & 1;
    const int pidx = tid >> 1;
    // GEMM2 roles: 8 point-groups (q3, 32 pts) x 16 cluster-quads (c4) x ph
    const int q3 = tid >> 5;
    const int c4 = (tid & 31) >> 1;
    const int ph = tid & 1;

    ull macc[4][8];
    #pragma unroll
    for (int c = 0; c < 4; ++c)
        #pragma unroll
        for (int j = 0; j < 8; ++j) macc[c][j] = 0ull;
    float nacc[4] = {0.f, 0.f, 0.f, 0.f};
    ull es2[4] = {0ull, 0ull, 0ull, 0ull};

    const int tiles = (N + TILE - 1) >> 8;

    for (int tile = blockIdx.x; tile < tiles; tile += gridDim.x) {
        __syncthreads();   // previous iteration's readers done before overwrite
        const int t0 = tile << 8;
        int vpts = N - t0; if (vpts > TILE) vpts = TILE;
        const int vflt = vpts * PD;

        // ---- coalesced stage-in: mu_phi -> ASM, exp(lcp) -> ECs ----
        {
            const float* src = mu_phi + (size_t)t0 * PD;
            #pragma unroll
            for (int c = 0; c < 8; ++c) {
                int idx = c * 1024 + tid * 4;
                float4 v = make_float4(0.f, 0.f, 0.f, 0.f);
                if (idx < vflt) v = *(const float4*)(src + idx);
                *(float4*)(ASMf + (idx >> 5) * 36 + (idx & 31)) = v;
            }
            int i = t0 + tid;
            ECs[tid] = (i < N) ? __expf(lcp_g[i]) : 0.f;
        }
        __syncthreads();

        // ---- GEMM1: 2 passes; per pass 1 point x 32 clusters (acc[16]) ----
        #pragma unroll 1
        for (int pass = 0; pass < 2; ++pass) {
            const int pt = pidx + (pass << 7);
            const float* row = ASMf + pt * 36;
            ull acc[16];
            #pragma unroll
            for (int j = 0; j < 16; ++j) acc[j] = 0ull;
            float na = 0.0f;

            #pragma unroll 4
            for (int pp = 0; pp < 16; ++pp) {
                float2 f = *(const float2*)(row + 2 * pp);
                na = fmaf(f.x, f.x, fmaf(f.y, f.y, na));
                ull ax = pk2(f.x, f.x), ay = pk2(f.y, f.y);
                const ulonglong2* mk0 = (const ulonglong2*)(MUK2 + (2 * pp) * 32 + 16 * s);
                const ulonglong2* mk1 = (const ulonglong2*)(MUK2 + (2 * pp + 1) * 32 + 16 * s);
                #pragma unroll
                for (int qq = 0; qq < 8; ++qq) {
                    ulonglong2 m0 = mk0[qq];
                    acc[2 * qq]     = fma2(ax, m0.x, acc[2 * qq]);
                    acc[2 * qq + 1] = fma2(ax, m0.y, acc[2 * qq + 1]);
                    ulonglong2 m1 = mk1[qq];
                    acc[2 * qq]     = fma2(ay, m1.x, acc[2 * qq]);
                    acc[2 * qq + 1] = fma2(ay, m1.y, acc[2 * qq + 1]);
                }
            }
            NAs[pt] = na;   // both s-lanes write identical value

            // epilogue: w for 32 clusters, full wsum via 1 shfl, gamma -> GR
            float ec = ECs[pt];
            float tP = 32.0f * ec;
            float wsum = 0.0f;
            #pragma unroll
            for (int j = 0; j < 16; ++j) {
                int k0 = 32 * s + 2 * j;
                float d0, d1; upk2(acc[j], d0, d1);
                float sq0 = na - 2.0f * d0 + NB[k0];
                float sq1 = na - 2.0f * d1 + NB[k0 + 1];
                float w0 = AK[k0]     * __expf(-0.5f * ICOV[k0]     * (tP + sq0));
                float w1 = AK[k0 + 1] * __expf(-0.5f * ICOV[k0 + 1] * (tP + sq1));
                wsum += w0 + w1;
                acc[j] = pk2(w0, w1);
            }
            wsum += __shfl_xor_sync(0xffffffffu, wsum, 1);
            bool valid = (t0 + pt) < N;
            float rs = valid ? 1.0f / wsum : 0.0f;
            float dt = valid ? DETC : 0.0f;
            ull rs2 = pk2(rs, rs), dt2 = pk2(dt, dt);
            #pragma unroll
            for (int ql = 0; ql < 8; ++ql) {
                ull h0 = fma2(acc[2 * ql],     rs2, dt2);
                ull h1 = fma2(acc[2 * ql + 1], rs2, dt2);
                float4 v; upk2(h0, v.x, v.y); upk2(h1, v.z, v.w);
                int qd = 8 * s + ql;
                *(float4*)(GRf + pt * 64 + 4 * (qd ^ (pt & 15))) = v;
            }
        }
        __syncthreads();

        // ---- coalesced gamma store: GR -> global (de-swizzle) ----
        {
            float* gdst = gamma_out + (size_t)t0 * KCL;
            const int vf = vpts * KCL;
            #pragma unroll
            for (int c = 0; c < 16; ++c) {
                int o4 = c * 256 + tid;          // float4 index
                if (4 * o4 < vf) {
                    int pt = o4 >> 4, qd = o4 & 15;
                    float4 v = *(const float4*)(GRf + pt * 64 + 4 * (qd ^ (pt & 15)));
                    *(float4*)(gdst + 4 * o4) = v;
                }
            }
        }

        // ---- GEMM2: 4 clusters x p-half per thread, 32 pts per warp ----
        {
            #pragma unroll 2
            for (int u = 0; u < 32; ++u) {
                const int pt = q3 * 32 + u;
                const ulonglong2* ap = (const ulonglong2*)(ASMu + pt * 18 + ph * 8);
                ulonglong2 A0 = ap[0], A1 = ap[1], A2 = ap[2], A3 = ap[3];
                ull ar[8] = {A0.x, A0.y, A1.x, A1.y, A2.x, A2.y, A3.x, A3.y};
                float4 g4 = *(const float4*)(GRf + pt * 64 + 4 * (c4 ^ (pt & 15)));
                float gg[4] = {g4.x, g4.y, g4.z, g4.w};
                #pragma unroll
                for (int c = 0; c < 4; ++c) {
                    ull g2 = pk2(gg[c], gg[c]);
                    #pragma unroll
                    for (int j = 0; j < 8; ++j)
                        macc[c][j] = fma2(g2, ar[j], macc[c][j]);
                }
                if (ph == 0) {
                    ull en = pk2(ECs[pt], NAs[pt]);
                    #pragma unroll
                    for (int c = 0; c < 4; ++c) {
                        nacc[c] += gg[c];
                        es2[c] = fma2(pk2(gg[c], gg[c]), en, es2[c]);
                    }
                }
            }
        }
    }

    // ---- combine partials across the 8 point-groups (reuse smem) ----
    __syncthreads();
    ull*   SB = (ull*)sm;                    // 256*32 ull = 64 KB
    float* SN = (float*)(sm + 65536);        // 512 floats
    float* SE = SN + 512;
    float* SS = SE + 512;
    #pragma unroll
    for (int c = 0; c < 4; ++c)
        #pragma unroll
        for (int j = 0; j < 8; ++j)
            SB[tid * 32 + c * 8 + j] = macc[c][j];
    if (ph == 0) {
        int b = q3 * 64 + c4 * 4;
        #pragma unroll
        for (int c = 0; c < 4; ++c) {
            float e, s2; upk2(es2[c], e, s2);
            SN[b + c] = nacc[c]; SE[b + c] = e; SS[b + c] = s2;
        }
    }
    __syncthreads();

    float* my = g_scratch + (size_t)blockIdx.x * NENT;
    for (int o = tid; o < 1024; o += 256) {
        int k = o >> 4, jp = o & 15;
        int cc = k >> 2, c = k & 3, hh = jp >> 3, j = jp & 7;
        float s0 = 0.f, s1 = 0.f;
        #pragma unroll
        for (int q = 0; q < 8; ++q) {
            float x0, x1;
            upk2(SB[(q * 32 + cc * 2 + hh) * 32 + c * 8 + j], x0, x1);
            s0 += x0; s1 += x1;
        }
        my[k * PD + 2 * jp]     = s0;
        my[k * PD + 2 * jp + 1] = s1;
    }
    if (tid < KCL) {
        float n = 0.f, e = 0.f, s2 = 0.f;
        #pragma unroll
        for (int q = 0; q < 8; ++q) {
            n += SN[q * 64 + tid]; e += SE[q * 64 + tid]; s2 += SS[q * 64 + tid];
        }
        my[2048 + tid] = n;
        my[2112 + tid] = e;
        my[2176 + tid] = s2;
    }
}

// Stage 1: reduce g_scratch[nblk][NENT] -> g_acc[NENT], coalesced + MLP=4.
__global__ __launch_bounds__(256)
void deeplpm_reduce(int nblk) {
    int e = blockIdx.x * 256 + threadIdx.x;
    if (e >= NENT) return;
    const float* p = g_scratch + e;
    float s0 = 0.f, s1 = 0.f, s2 = 0.f, s3 = 0.f;
    int b = 0;
    for (; b + 4 <= nblk; b += 4) {
        s0 += p[(size_t)(b + 0) * NENT];
        s1 += p[(size_t)(b + 1) * NENT];
        s2 += p[(size_t)(b + 2) * NENT];
        s3 += p[(size_t)(b + 3) * NENT];
    }
    for (; b < nblk; ++b) s0 += p[(size_t)b * NENT];
    g_acc[e] = (s0 + s1) + (s2 + s3);
}

// Stage 2: final per-cluster math.
__global__ __launch_bounds__(64)
void deeplpm_finalize(float* __restrict__ pi_out,
                      float* __restrict__ mu_out,
                      float* __restrict__ lc_out,
                      int N) {
    int t = threadIdx.x;
    if (t >= KCL) return;
    float Nk = g_acc[2048 + t];
    float Ek = g_acc[2112 + t];
    float Sk = g_acc[2176 + t];
    pi_out[t] = Nk / (float)N;
    float inv = 1.0f / Nk;
    float nm2 = 0.0f;
    #pragma unroll
    for (int p = 0; p < PD; ++p) {
        float m = g_acc[t * PD + p] * inv;
        mu_out[t * PD + p] = m;
        nm2 = fmaf(m, m, nm2);
    }
    float cov = (32.0f * Ek + Sk - Nk * nm2) / (32.0f * Nk);
    lc_out[t] = logf(cov);
}

extern "C" void kernel_launch(void* const* d_in, const int* in_sizes, int n_in,
                              void* d_out, int out_size) {
    const float* mu_phi = (const float*)d_in[0];
    const float* lcp    = (const float*)d_in[1];
    const float* pi_k   = (const float*)d_in[2];
    const float* mu_k   = (const float*)d_in[3];
    const float* lck    = (const float*)d_in[4];
    const int N = in_sizes[0] / PD;

    float* out     = (float*)d_out;
    float* gamma_o = out;
    float* pi_o    = out + (size_t)N * KCL;
    float* mu_o    = pi_o + KCL;
    float* lc_o    = mu_o + KCL * PD;

    int tiles = (N + TILE - 1) / TILE;
    int grid  = tiles < NBLK ? tiles : NBLK;

    cudaFuncSetAttribute(deeplpm_main,
                         cudaFuncAttributeMaxDynamicSharedMemorySize, SMEM_BYTES);

    deeplpm_main<<<grid, 256, SMEM_BYTES>>>(mu_phi, lcp, pi_k, mu_k, lck,
                                            gamma_o, N);
    deeplpm_reduce<<<(NENT + 255) / 256, 256>>>(grid);
    deeplpm_finalize<<<1, 64>>>(pi_o, mu_o, lc_o, N);
}

// round 11
// speedup vs baseline: 1.3628x; 1.3628x over previous
#include <cuda_runtime.h>

#define KCL   64
#define PD    32
#define NBLK  296
#define TILE  256
#define DETC  1e-16f
#define NENT  2240

typedef unsigned long long ull;

// ---- shared memory layout (bytes) ----
#define OFF_MUK2 0          // ull[1024]  mu_k packed cluster-pairs [p][pair]  8192 B
#define OFF_ASM  8192       // 256 rows * 18 ull (mu_phi, pitch 36 floats)   36864 B
#define OFF_GT   45056      // float[64*257 + 16] gamma transposed, s-offset 65856 B
#define OFF_ECNA 110912     // float[512]: (exp(lcp), ||x||^2) interleaved    2048 B
#define OFF_AK   112960     // float[64]
#define OFF_ICOV 113216     // float[64]
#define OFF_NB   113472     // float[64]
#define SMEM_BYTES 113728

// per-block partials, layout [block][entry]:
// 0..2047 = M[k][p], 2048..2111 = N_k, 2112..2175 = E_k, 2176..2239 = S2_k
__device__ float g_scratch[NBLK * NENT];
__device__ float g_acc[NENT];

__device__ __forceinline__ ull pk2(float lo, float hi) {
    ull u; asm("mov.b64 %0, {%1,%2};" : "=l"(u) : "f"(lo), "f"(hi)); return u;
}
__device__ __forceinline__ void upk2(ull u, float& lo, float& hi) {
    asm("mov.b64 {%0,%1}, %2;" : "=f"(lo), "=f"(hi) : "l"(u));
}
__device__ __forceinline__ ull fma2(ull a, ull b, ull c) {
    ull d; asm("fma.rn.f32x2 %0, %1, %2, %3;" : "=l"(d) : "l"(a), "l"(b), "l"(c));
    return d;
}

__global__ __launch_bounds__(256, 1)
void deeplpm_main(const float* __restrict__ mu_phi,
                  const float* __restrict__ lcp_g,
                  const float* __restrict__ pi_k,
                  const float* __restrict__ mu_k,
                  const float* __restrict__ lck_g,
                  float* __restrict__ gamma_out,
                  int N) {
    extern __shared__ unsigned char sm[];
    ull*   MUK2  = (ull*)(sm + OFF_MUK2);
    float* ASMf  = (float*)(sm + OFF_ASM);   // pitch 36 floats per point
    ull*   ASMu  = (ull*)(sm + OFF_ASM);     // pitch 18 ull per point
    float* GT    = (float*)(sm + OFF_GT);    // GT[k*257 + pt + 16*(k>>5)]
    float* ECNA2 = (float*)(sm + OFF_ECNA);  // [2*pt] = ec, [2*pt+1] = na
    float* AK    = (float*)(sm + OFF_AK);
    float* ICOV  = (float*)(sm + OFF_ICOV);
    float* NB    = (float*)(sm + OFF_NB);

    const int tid = threadIdx.x;

    // ---- init tables ----
    for (int idx = tid; idx < 1024; idx += 256) {
        int pr = idx & 31, p = idx >> 5;
        MUK2[p * 32 + pr] = pk2(mu_k[(2 * pr) * PD + p], mu_k[(2 * pr + 1) * PD + p]);
    }
    if (tid < KCL) {
        float lck = lck_g[tid];
        ICOV[tid] = __expf(-lck);
        AK[tid]   = pi_k[tid] * __expf(-16.0f * lck);
        float nb = 0.0f;
        #pragma unroll
        for (int p = 0; p < PD; ++p) { float v = mu_k[tid * PD + p]; nb = fmaf(v, v, nb); }
        NB[tid] = nb;
    }

    // GEMM1 roles: s = cluster half, pidx = point owner (points pidx, pidx+128)
    const int s    = tid & 1;
    const int pidx = tid >> 1;
    // GEMM2 roles (R3/R8 scheme): 4 point-quarters (q) x 32 kp x 2 ph
    const int q  = tid >> 6;
    const int r  = tid & 63;
    const int kp = r >> 1;
    const int ph = r & 1;
    const int gr0 = (2 * kp) * 257 + 16 * (kp >> 4);
    const int gr1 = gr0 + 257;

    ull macc0[8], macc1[8];
    #pragma unroll
    for (int j = 0; j < 8; ++j) { macc0[j] = 0ull; macc1[j] = 0ull; }
    float nacc = 0.0f;
    ull   esacc = 0ull;               // (E_k, S2_k) packed

    const int tiles = (N + TILE - 1) >> 8;

    for (int tile = blockIdx.x; tile < tiles; tile += gridDim.x) {
        __syncthreads();   // previous iteration's readers done before overwrite
        const int t0 = tile << 8;
        int vpts = N - t0; if (vpts > TILE) vpts = TILE;
        const int vflt = vpts * PD;

        // ---- coalesced stage-in: mu_phi -> ASM, exp(lcp) -> ECNA2 ----
        {
            const float* src = mu_phi + (size_t)t0 * PD;
            #pragma unroll
            for (int c = 0; c < 8; ++c) {
                int idx = c * 1024 + tid * 4;
                float4 v = make_float4(0.f, 0.f, 0.f, 0.f);
                if (idx < vflt) v = *(const float4*)(src + idx);
                *(float4*)(ASMf + (idx >> 5) * 36 + (idx & 31)) = v;
            }
            int i = t0 + tid;
            ECNA2[2 * tid] = (i < N) ? __expf(lcp_g[i]) : 0.f;
        }
        __syncthreads();

        // ---- GEMM1: 2 points x 32 clusters per thread (single table pass) ----
        ull accA[16], accB[16];
        #pragma unroll
        for (int j = 0; j < 16; ++j) { accA[j] = 0ull; accB[j] = 0ull; }
        float naA = 0.0f, naB = 0.0f;
        const float* rowA = ASMf + pidx * 36;
        const float* rowB = ASMf + (pidx + 128) * 36;

        #pragma unroll 2
        for (int pp = 0; pp < 16; ++pp) {
            float2 fa = *(const float2*)(rowA + 2 * pp);
            float2 fb = *(const float2*)(rowB + 2 * pp);
            naA = fmaf(fa.x, fa.x, fmaf(fa.y, fa.y, naA));
            naB = fmaf(fb.x, fb.x, fmaf(fb.y, fb.y, naB));
            ull axA = pk2(fa.x, fa.x), ayA = pk2(fa.y, fa.y);
            ull axB = pk2(fb.x, fb.x), ayB = pk2(fb.y, fb.y);
            const ulonglong2* mk0 = (const ulonglong2*)(MUK2 + (2 * pp) * 32 + 16 * s);
            const ulonglong2* mk1 = (const ulonglong2*)(MUK2 + (2 * pp + 1) * 32 + 16 * s);
            #pragma unroll
            for (int qq = 0; qq < 8; ++qq) {
                ulonglong2 m0 = mk0[qq];
                accA[2 * qq]     = fma2(axA, m0.x, accA[2 * qq]);
                accA[2 * qq + 1] = fma2(axA, m0.y, accA[2 * qq + 1]);
                accB[2 * qq]     = fma2(axB, m0.x, accB[2 * qq]);
                accB[2 * qq + 1] = fma2(axB, m0.y, accB[2 * qq + 1]);
                ulonglong2 m1 = mk1[qq];
                accA[2 * qq]     = fma2(ayA, m1.x, accA[2 * qq]);
                accA[2 * qq + 1] = fma2(ayA, m1.y, accA[2 * qq + 1]);
                accB[2 * qq]     = fma2(ayB, m1.x, accB[2 * qq]);
                accB[2 * qq + 1] = fma2(ayB, m1.y, accB[2 * qq + 1]);
            }
        }
        ECNA2[2 * pidx + 1]         = naA;   // both s-lanes write same value
        ECNA2[2 * (pidx + 128) + 1] = naB;

        // ---- epilogue point A ----
        {
            float ec = ECNA2[2 * pidx];
            float tP = 32.0f * ec;
            float wsum = 0.0f;
            #pragma unroll
            for (int j = 0; j < 16; ++j) {
                int k0 = 32 * s + 2 * j;
                float d0, d1; upk2(accA[j], d0, d1);
                float sq0 = naA - 2.0f * d0 + NB[k0];
                float sq1 = naA - 2.0f * d1 + NB[k0 + 1];
                float w0 = AK[k0]     * __expf(-0.5f * ICOV[k0]     * (tP + sq0));
                float w1 = AK[k0 + 1] * __expf(-0.5f * ICOV[k0 + 1] * (tP + sq1));
                wsum += w0 + w1;
                accA[j] = pk2(w0, w1);
            }
            wsum += __shfl_xor_sync(0xffffffffu, wsum, 1);
            bool valid = (t0 + pidx) < N;
            float rs = valid ? 1.0f / wsum : 0.0f;
            float dt = valid ? DETC : 0.0f;
            ull rs2 = pk2(rs, rs), dt2 = pk2(dt, dt);
            #pragma unroll
            for (int j = 0; j < 16; ++j) {
                float g0, g1;
                upk2(fma2(accA[j], rs2, dt2), g0, g1);
                int kb = (32 * s + 2 * j) * 257 + 16 * s + pidx;
                GT[kb]       = g0;
                GT[kb + 257] = g1;
            }
        }
        // ---- epilogue point B ----
        {
            float ec = ECNA2[2 * (pidx + 128)];
            float tP = 32.0f * ec;
            float wsum = 0.0f;
            #pragma unroll
            for (int j = 0; j < 16; ++j) {
                int k0 = 32 * s + 2 * j;
                float d0, d1; upk2(accB[j], d0, d1);
                float sq0 = naB - 2.0f * d0 + NB[k0];
                float sq1 = naB - 2.0f * d1 + NB[k0 + 1];
                float w0 = AK[k0]     * __expf(-0.5f * ICOV[k0]     * (tP + sq0));
                float w1 = AK[k0 + 1] * __expf(-0.5f * ICOV[k0 + 1] * (tP + sq1));
                wsum += w0 + w1;
                accB[j] = pk2(w0, w1);
            }
            wsum += __shfl_xor_sync(0xffffffffu, wsum, 1);
            bool valid = (t0 + pidx + 128) < N;
            float rs = valid ? 1.0f / wsum : 0.0f;
            float dt = valid ? DETC : 0.0f;
            ull rs2 = pk2(rs, rs), dt2 = pk2(dt, dt);
            #pragma unroll
            for (int j = 0; j < 16; ++j) {
                float g0, g1;
                upk2(fma2(accB[j], rs2, dt2), g0, g1);
                int kb = (32 * s + 2 * j) * 257 + 16 * s + pidx + 128;
                GT[kb]       = g0;
                GT[kb + 257] = g1;
            }
        }
        __syncthreads();

        // ---- coalesced gamma store: GT -> global ----
        {
            float* gdst = gamma_out + (size_t)t0 * KCL;
            const int vf = vpts * KCL;
            #pragma unroll
            for (int c = 0; c < 16; ++c) {
                int o4 = c * 256 + tid;          // float4 index
                if (4 * o4 < vf) {
                    int pt = o4 >> 4, kq = (o4 & 15) * 4;
                    int off = 16 * (kq >> 5) + pt;
                    float4 v;
                    v.x = GT[(kq + 0) * 257 + off];
                    v.y = GT[(kq + 1) * 257 + off];
                    v.z = GT[(kq + 2) * 257 + off];
                    v.w = GT[(kq + 3) * 257 + off];
                    *(float4*)(gdst + 4 * o4) = v;
                }
            }
        }

        // ---- GEMM2: gamma^T @ mu_phi tile + stats ----
        {
            const int pb = q * 64;
            for (int u = 0; u < 64; ++u) {
                int pt = pb + u;
                float g0 = GT[gr0 + pt];
                float g1 = GT[gr1 + pt];
                ull ga = pk2(g0, g0), gb = pk2(g1, g1);
                const ulonglong2* ap = (const ulonglong2*)(ASMu + pt * 18 + ph * 8);
                ulonglong2 A0 = ap[0], A1 = ap[1], A2 = ap[2], A3 = ap[3];
                ull ar[8] = {A0.x, A0.y, A1.x, A1.y, A2.x, A2.y, A3.x, A3.y};
                #pragma unroll
                for (int j = 0; j < 8; ++j) {
                    macc0[j] = fma2(ga, ar[j], macc0[j]);
                    macc1[j] = fma2(gb, ar[j], macc1[j]);
                }
                float gk = ph ? g1 : g0;         // stats for cluster k == r
                nacc += gk;
                ull en = *(const ull*)(ECNA2 + 2 * pt);
                esacc = fma2(pk2(gk, gk), en, esacc);
            }
        }
    }

    // ---- block-level combine of the 4 point-quarter partials ----
    __syncthreads();
    float eacc, sacc;
    upk2(esacc, eacc, sacc);
    ull*   SB  = (ull*)sm;                  // 256*16 ull = 32 KB (reuse)
    float* SSn = (float*)(sm + 32768);
    float* SSe = SSn + 256;
    float* SSs = SSe + 256;
    #pragma unroll
    for (int j = 0; j < 8; ++j) {
        SB[tid * 16 + j]     = macc0[j];
        SB[tid * 16 + 8 + j] = macc1[j];
    }
    SSn[tid] = nacc; SSe[tid] = eacc; SSs[tid] = sacc;
    __syncthreads();

    float* my = g_scratch + (size_t)blockIdx.x * NENT;
    for (int o = tid; o < 1024; o += 256) {
        int ro = o >> 4, jo = o & 15;
        float s0 = 0.0f, s1 = 0.0f;
        #pragma unroll
        for (int qq = 0; qq < 4; ++qq) {
            float x0, x1;
            upk2(SB[((qq << 6) | ro) * 16 + jo], x0, x1);
            s0 += x0; s1 += x1;
        }
        int kk = 2 * (ro >> 1) + (jo >> 3);
        int pp = 2 * (((ro & 1) << 3) + (jo & 7));
        my[kk * PD + pp]     = s0;
        my[kk * PD + pp + 1] = s1;
    }
    if (tid < KCL) {
        float n = 0.f, e = 0.f, s2 = 0.f;
        #pragma unroll
        for (int qq = 0; qq < 4; ++qq) {
            n  += SSn[(qq << 6) | tid];
            e  += SSe[(qq << 6) | tid];
            s2 += SSs[(qq << 6) | tid];
        }
        my[2048 + tid] = n;
        my[2112 + tid] = e;
        my[2176 + tid] = s2;
    }
}

// Stage 1: reduce g_scratch[nblk][NENT] -> g_acc[NENT], coalesced + MLP=4.
__global__ __launch_bounds__(256)
void deeplpm_reduce(int nblk) {
    int e = blockIdx.x * 256 + threadIdx.x;
    if (e >= NENT) return;
    const float* p = g_scratch + e;
    float s0 = 0.f, s1 = 0.f, s2 = 0.f, s3 = 0.f;
    int b = 0;
    for (; b + 4 <= nblk; b += 4) {
        s0 += p[(size_t)(b + 0) * NENT];
        s1 += p[(size_t)(b + 1) * NENT];
        s2 += p[(size_t)(b + 2) * NENT];
        s3 += p[(size_t)(b + 3) * NENT];
    }
    for (; b < nblk; ++b) s0 += p[(size_t)b * NENT];
    g_acc[e] = (s0 + s1) + (s2 + s3);
}

// Stage 2: final per-cluster math.
__global__ __launch_bounds__(64)
void deeplpm_finalize(float* __restrict__ pi_out,
                      float* __restrict__ mu_out,
                      float* __restrict__ lc_out,
                      int N) {
    int t = threadIdx.x;
    if (t >= KCL) return;
    float Nk = g_acc[2048 + t];
    float Ek = g_acc[2112 + t];
    float Sk = g_acc[2176 + t];
    pi_out[t] = Nk / (float)N;
    float inv = 1.0f / Nk;
    float nm2 = 0.0f;
    #pragma unroll
    for (int p = 0; p < PD; ++p) {
        float m = g_acc[t * PD + p] * inv;
        mu_out[t * PD + p] = m;
        nm2 = fmaf(m, m, nm2);
    }
    float cov = (32.0f * Ek + Sk - Nk * nm2) / (32.0f * Nk);
    lc_out[t] = logf(cov);
}

extern "C" void kernel_launch(void* const* d_in, const int* in_sizes, int n_in,
                              void* d_out, int out_size) {
    const float* mu_phi = (const float*)d_in[0];
    const float* lcp    = (const float*)d_in[1];
    const float* pi_k   = (const float*)d_in[2];
    const float* mu_k   = (const float*)d_in[3];
    const float* lck    = (const float*)d_in[4];
    const int N = in_sizes[0] / PD;

    float* out     = (float*)d_out;
    float* gamma_o = out;
    float* pi_o    = out + (size_t)N * KCL;
    float* mu_o    = pi_o + KCL;
    float* lc_o    = mu_o + KCL * PD;

    int tiles = (N + TILE - 1) / TILE;
    int grid  = tiles < NBLK ? tiles : NBLK;

    cudaFuncSetAttribute(deeplpm_main,
                         cudaFuncAttributeMaxDynamicSharedMemorySize, SMEM_BYTES);

    deeplpm_main<<<grid, 256, SMEM_BYTES>>>(mu_phi, lcp, pi_k, mu_k, lck,
                                            gamma_o, N);
    deeplpm_reduce<<<(NENT + 255) / 256, 256>>>(grid);
    deeplpm_finalize<<<1, 64>>>(pi_o, mu_o, lc_o, N);
}